// round 12
// baseline (speedup 1.0000x reference)
#include <cuda_runtime.h>
#include <cuda_bf16.h>
#include <cstdint>
#include <cstddef>

// Problem constants
#define BATCH 4
#define C_IN  256
#define CI    128
#define NPIX  4096   // 64*64
#define NT    128    // n-rows per attn CTA
#define MT    64     // m-chunk
#define NCHUNK (NPIX / MT)   // 64

// ---------------------------------------------------------------------------
// Scratch (allocation-free: __device__ globals)
// ---------------------------------------------------------------------------
__device__ __nv_bfloat16 g_Thi[(size_t)BATCH * NPIX * CI];  // theta(a) [B][n][ci]
__device__ __nv_bfloat16 g_Tlo[(size_t)BATCH * NPIX * CI];
__device__ __nv_bfloat16 g_Phh[(size_t)BATCH * NPIX * CI];  // phi(b)   [B][m][ci]
__device__ __nv_bfloat16 g_Phl[(size_t)BATCH * NPIX * CI];
__device__ __nv_bfloat16 g_Ghi[(size_t)BATCH * CI * NPIX];  // g(b)     [B][ci][m]
__device__ __nv_bfloat16 g_Glo[(size_t)BATCH * CI * NPIX];
__device__ __nv_bfloat16 g_Yhi[(size_t)BATCH * NPIX * CI];  // y        [B][n][ci]
__device__ __nv_bfloat16 g_Ylo[(size_t)BATCH * NPIX * CI];

// ---------------------------------------------------------------------------
// PTX helpers (baseline features only: valid under compute_103)
// ---------------------------------------------------------------------------
__device__ __forceinline__ uint32_t smem_u32(const void* p) {
    uint32_t a;
    asm("{ .reg .u64 t; cvta.to.shared.u64 t, %1; cvt.u32.u64 %0, t; }"
        : "=r"(a) : "l"(p));
    return a;
}

#define LDM_X4(r, a)                                                          \
    asm volatile("ldmatrix.sync.aligned.m8n8.x4.shared.b16 {%0,%1,%2,%3}, [%4];" \
        : "=r"((r)[0]), "=r"((r)[1]), "=r"((r)[2]), "=r"((r)[3]) : "r"(a))

__device__ __forceinline__ void mma16816(float* d, const uint32_t* a,
                                         uint32_t b0, uint32_t b1) {
    asm("mma.sync.aligned.m16n8k16.row.col.f32.bf16.bf16.f32 "
        "{%0,%1,%2,%3}, {%4,%5,%6,%7}, {%8,%9}, {%0,%1,%2,%3};"
        : "+f"(d[0]), "+f"(d[1]), "+f"(d[2]), "+f"(d[3])
        : "r"(a[0]), "r"(a[1]), "r"(a[2]), "r"(a[3]), "r"(b0), "r"(b1));
}

#define CP16(dst, src)                                                        \
    asm volatile("cp.async.cg.shared.global [%0], [%1], 16;"                  \
                 :: "r"(dst), "l"(src) : "memory")
#define CP_COMMIT() asm volatile("cp.async.commit_group;" ::: "memory")
#define CP_WAIT0()  asm volatile("cp.async.wait_group 0;" ::: "memory")

// bf16 split helpers
__device__ __forceinline__ uint32_t pk(float a, float b) {
    uint32_t ua = (uint32_t)__bfloat16_as_ushort(__float2bfloat16(a));
    uint32_t ub = (uint32_t)__bfloat16_as_ushort(__float2bfloat16(b));
    return ua | (ub << 16);
}
__device__ __forceinline__ float resid(float v) {
    return v - __bfloat162float(__float2bfloat16(v));
}
__device__ __forceinline__ void split2(float a, float b,
                                       uint32_t& hi, uint32_t& lo) {
    __nv_bfloat16 ha = __float2bfloat16(a), hb = __float2bfloat16(b);
    hi = (uint32_t)__bfloat16_as_ushort(ha) |
         ((uint32_t)__bfloat16_as_ushort(hb) << 16);
    lo = pk(a - __bfloat162float(ha), b - __bfloat162float(hb));
}

// 6 split-bf16 MMAs for one 16-col B panel, interleaved accumulators
__device__ __forceinline__ void mma6(float* d0, float* d1,
                                     const uint32_t* ah, const uint32_t* al,
                                     const uint32_t* bh, const uint32_t* bl) {
    mma16816(d0, ah, bh[0], bh[1]);
    mma16816(d1, ah, bh[2], bh[3]);
    mma16816(d0, ah, bl[0], bl[1]);
    mma16816(d1, ah, bl[2], bl[3]);
    mma16816(d0, al, bh[0], bh[1]);
    mma16816(d1, al, bh[2], bh[3]);
}

// ---------------------------------------------------------------------------
// proj (HMMA): out = w[CI,C] @ x[b][C,:] + bias, split-bf16 emulation.
// TRANS=1 -> out[b][n][ci] (theta/phi) ; TRANS=0 -> out[b][ci][n] (g)
// ---------------------------------------------------------------------------
#define PJ_PITCH 528u
#define PJ_XH 0u
#define PJ_XL 33792u
#define PJ_WH 67584u
#define PJ_WL 135168u
#define PJ_SMEM 202752u

template<int TRANS>
__global__ __launch_bounds__(256)
void proj_mma_kernel(const float* __restrict__ x, const float* __restrict__ w,
                     const float* __restrict__ bias,
                     __nv_bfloat16* __restrict__ outHi,
                     __nv_bfloat16* __restrict__ outLo) {
    extern __shared__ char psm[];
    const uint32_t sb = smem_u32(psm);
    const int tid = threadIdx.x, lane = tid & 31, wid = tid >> 5;
    const int bb = blockIdx.y, n0 = blockIdx.x * 64;

#pragma unroll
    for (int i = 0; i < 16; i++) {
        int idx = tid + i * 256;
        int c = idx >> 4, n4 = idx & 15;
        float4 v = *(const float4*)&x[((size_t)bb * C_IN + c) * NPIX + n0 + 4 * n4];
        float vv[4] = {v.x, v.y, v.z, v.w};
#pragma unroll
        for (int j = 0; j < 4; j++) {
            __nv_bfloat16 h = __float2bfloat16(vv[j]);
            uint32_t o = (uint32_t)(4 * n4 + j) * PJ_PITCH + 2u * (uint32_t)c;
            *(unsigned short*)(psm + PJ_XH + o) = __bfloat16_as_ushort(h);
            *(unsigned short*)(psm + PJ_XL + o) =
                __bfloat16_as_ushort(__float2bfloat16(vv[j] - __bfloat162float(h)));
        }
    }
#pragma unroll
    for (int i = 0; i < 32; i++) {
        int idx = tid + i * 256;
        int r = idx >> 6, c4 = idx & 63;
        float4 v = *(const float4*)&w[(size_t)r * C_IN + 4 * c4];
        uint2 H, L;
        H.x = pk(v.x, v.y); H.y = pk(v.z, v.w);
        L.x = pk(resid(v.x), resid(v.y)); L.y = pk(resid(v.z), resid(v.w));
        uint32_t o = (uint32_t)r * PJ_PITCH + 8u * (uint32_t)c4;
        *(uint2*)(psm + PJ_WH + o) = H;
        *(uint2*)(psm + PJ_WL + o) = L;
    }
    __syncthreads();

    const int lm = lane & 7, mid = lane >> 3;
    const int arow = (mid & 1) * 8 + lm, acolB = (mid >> 1) * 16;
    const int brow = (mid >> 1) * 8 + lm, bcolB = (mid & 1) * 16;

    uint32_t aBase, bBase, aLd, bLd;
    if (TRANS) {
        int mi = wid & 3, ch = wid >> 2;
        aBase = sb + PJ_XH + (uint32_t)(mi * 16 + arow) * PJ_PITCH + acolB;
        bBase = sb + PJ_WH + (uint32_t)(ch * 64 + brow) * PJ_PITCH + bcolB;
        aLd = PJ_XL - PJ_XH; bLd = PJ_WL - PJ_WH;
    } else {
        aBase = sb + PJ_WH + (uint32_t)(wid * 16 + arow) * PJ_PITCH + acolB;
        bBase = sb + PJ_XH + (uint32_t)brow * PJ_PITCH + bcolB;
        aLd = PJ_WL - PJ_WH; bLd = PJ_XL - PJ_XH;
    }

    float acc[8][4];
#pragma unroll
    for (int j = 0; j < 8; j++)
#pragma unroll
        for (int q = 0; q < 4; q++) acc[j][q] = 0.f;

#pragma unroll 4
    for (int kk = 0; kk < 16; kk++) {
        uint32_t ah[4], al[4];
        LDM_X4(ah, aBase + 32u * kk);
        LDM_X4(al, aBase + aLd + 32u * kk);
#pragma unroll
        for (int p = 0; p < 4; p++) {
            uint32_t bh[4], bl[4];
            uint32_t ba = bBase + (uint32_t)(16 * p) * PJ_PITCH + 32u * kk;
            LDM_X4(bh, ba);
            LDM_X4(bl, ba + bLd);
            mma6(acc[2 * p], acc[2 * p + 1], ah, al, bh, bl);
        }
    }

    const int gq = lane >> 2, tig = lane & 3;
    if (TRANS) {
        int mi = wid & 3, ch = wid >> 2;
        int nA = n0 + mi * 16 + gq;
#pragma unroll
        for (int j = 0; j < 8; j++) {
            int ci = ch * 64 + j * 8 + 2 * tig;
            float b0 = bias[ci], b1 = bias[ci + 1];
            uint32_t h, l;
            size_t o = ((size_t)bb * NPIX + nA) * CI + ci;
            split2(acc[j][0] + b0, acc[j][1] + b1, h, l);
            *(uint32_t*)(outHi + o) = h; *(uint32_t*)(outLo + o) = l;
            split2(acc[j][2] + b0, acc[j][3] + b1, h, l);
            o += (size_t)8 * CI;
            *(uint32_t*)(outHi + o) = h; *(uint32_t*)(outLo + o) = l;
        }
    } else {
        int ciA = wid * 16 + gq;
        float b0 = bias[ciA], b1 = bias[ciA + 8];
#pragma unroll
        for (int j = 0; j < 8; j++) {
            int n = n0 + j * 8 + 2 * tig;
            uint32_t h, l;
            size_t o = ((size_t)bb * CI + ciA) * NPIX + n;
            split2(acc[j][0] + b0, acc[j][1] + b0, h, l);
            *(uint32_t*)(outHi + o) = h; *(uint32_t*)(outLo + o) = l;
            split2(acc[j][2] + b1, acc[j][3] + b1, h, l);
            o += (size_t)8 * NPIX;
            *(uint32_t*)(outHi + o) = h; *(uint32_t*)(outLo + o) = l;
        }
    }
}

// ---------------------------------------------------------------------------
// attn (warp HMMA, 512 threads / 16 warps, S via smem):
// Y[b][n][ci] = sum_m (T[n][:].Phi[m][:]/N) * G[:, m]
// Phase A: warp (wq, wh) -> S[16wq..+16][32wh..+32], K=128
// Phase B: warp (wq, wh) -> Y[16wq..+16][64wh..+64], K=64 (S from smem)
// ---------------------------------------------------------------------------
#define T_PITCH   272u
#define G_PITCH   144u
#define OFF_THI   0u
#define OFF_TLO   34816u
#define OFF_PH    69632u     // 2 bufs x 34816 (hi +0, lo +17408)
#define PH_BUFSZ  34816u
#define PH_LO     17408u
#define OFF_G     139264u    // single buf (hi +0, lo +18432)
#define G_LO      18432u
#define OFF_S     176128u    // hi +0, lo +18432
#define S_LO      18432u
#define SMEM_BYTES 212992u

__device__ __forceinline__ void load_phi(uint32_t sb, int buf, int bb, int m0,
                                         int tid,
                                         const __nv_bfloat16* Phh,
                                         const __nv_bfloat16* Phl) {
    const uint32_t phiB = sb + OFF_PH + (uint32_t)buf * PH_BUFSZ;
#pragma unroll
    for (int i = 0; i < 2; i++) {
        int idx = tid + i * 512;
        int r = idx >> 4, c8 = idx & 15;
        size_t so = ((size_t)(bb * NPIX + m0 + r)) * CI + c8 * 8;
        uint32_t d = phiB + (uint32_t)r * T_PITCH + (uint32_t)c8 * 16u;
        CP16(d,          Phh + so);
        CP16(d + PH_LO,  Phl + so);
    }
}
__device__ __forceinline__ void load_g(uint32_t sb, int bb, int m0, int tid,
                                       const __nv_bfloat16* Ghi,
                                       const __nv_bfloat16* Glo) {
    const uint32_t gB = sb + OFF_G;
#pragma unroll
    for (int i = 0; i < 2; i++) {
        int idx = tid + i * 512;
        int ci = idx >> 3, m8 = idx & 7;
        size_t so = ((size_t)(bb * CI + ci)) * NPIX + m0 + m8 * 8;
        uint32_t d = gB + (uint32_t)ci * G_PITCH + (uint32_t)m8 * 16u;
        CP16(d,         Ghi + so);
        CP16(d + G_LO,  Glo + so);
    }
}

__global__ __launch_bounds__(512, 1)
void attn_hmma_kernel(const __nv_bfloat16* __restrict__ Thi,
                      const __nv_bfloat16* __restrict__ Tlo,
                      const __nv_bfloat16* __restrict__ Phh,
                      const __nv_bfloat16* __restrict__ Phl,
                      const __nv_bfloat16* __restrict__ Ghi,
                      const __nv_bfloat16* __restrict__ Glo,
                      __nv_bfloat16* __restrict__ Yhi,
                      __nv_bfloat16* __restrict__ Ylo) {
    extern __shared__ char smem[];
    const uint32_t sb = smem_u32(smem);
    const int tid  = threadIdx.x;
    const int wid  = tid >> 5;
    const int lane = tid & 31;
    const int bb   = blockIdx.y;
    const int n0   = blockIdx.x * NT;
    const int wq   = wid & 7;       // n-tile (16 rows)
    const int wh   = wid >> 3;      // half split (m in A, ci in B)

    const int lm  = lane & 7;
    const int mid = lane >> 3;
    const int arow = (mid & 1) * 8 + lm;
    const int acol = (mid >> 1) * 16;
    const int brow = (mid >> 1) * 8 + lm;
    const int bcol = (mid & 1) * 16;
    const int gq = lane >> 2, tig = lane & 3;

    // ---- prologue: T tile (hi+lo) + Phi[0] + G[0]
#pragma unroll
    for (int i = 0; i < 4; i++) {
        int idx = tid + i * 512;
        int r = idx >> 4, c8 = idx & 15;
        size_t so = ((size_t)(bb * NPIX + n0 + r)) * CI + c8 * 8;
        uint32_t d = sb + OFF_THI + (uint32_t)r * T_PITCH + (uint32_t)c8 * 16u;
        CP16(d,                       Thi + so);
        CP16(d + (OFF_TLO - OFF_THI), Tlo + so);
    }
    load_phi(sb, 0, bb, 0, tid, Phh, Phl);
    load_g(sb, bb, 0, tid, Ghi, Glo);
    CP_COMMIT();
    CP_WAIT0();
    __syncthreads();

    float yacc[8][4];
#pragma unroll
    for (int t = 0; t < 8; t++)
#pragma unroll
        for (int j = 0; j < 4; j++) yacc[t][j] = 0.f;

    const float invN = 1.0f / (float)NPIX;
    const uint32_t aHiBase = sb + OFF_THI +
        (uint32_t)(wq * 16 + arow) * T_PITCH + (uint32_t)acol;
    const uint32_t aSBase = sb + OFF_S +
        (uint32_t)(wq * 16 + arow) * G_PITCH + (uint32_t)acol;
    const uint32_t gBase = sb + OFF_G +
        (uint32_t)brow * G_PITCH + (uint32_t)bcol;

    for (int it = 0; it < NCHUNK; it++) {
        const int buf = it & 1;
        // prefetch Phi[it+1] (double buf) and G[it] was loaded last iter's tail;
        // here: G[it] for it==0 came from prologue; for it>0 issued below last iter.
        if (it + 1 < NCHUNK)
            load_phi(sb, buf ^ 1, bb, (it + 1) * MT, tid, Phh, Phl);
        CP_COMMIT();

        // ---- Phase A: S[16 n][32 m] = T . Phi^T  (K=128)
        float sacc[4][4];
#pragma unroll
        for (int j = 0; j < 4; j++)
#pragma unroll
            for (int q = 0; q < 4; q++) sacc[j][q] = 0.f;

        const uint32_t phiB = sb + OFF_PH + (uint32_t)buf * PH_BUFSZ +
                              (uint32_t)(wh * 32 + brow) * T_PITCH + (uint32_t)bcol;
#pragma unroll
        for (int kk = 0; kk < 8; kk++) {
            uint32_t ah[4], al[4];
            LDM_X4(ah, aHiBase + 32u * kk);
            LDM_X4(al, aHiBase + (OFF_TLO - OFF_THI) + 32u * kk);
#pragma unroll
            for (int p = 0; p < 2; p++) {
                uint32_t bh[4], bl[4];
                uint32_t ba = phiB + (uint32_t)(16 * p) * T_PITCH + 32u * kk;
                LDM_X4(bh, ba);
                LDM_X4(bl, ba + PH_LO);
                mma6(sacc[2 * p], sacc[2 * p + 1], ah, al, bh, bl);
            }
        }

        // ---- S epilogue: scale, split, store to smem [128 n][64 m] hi/lo
#pragma unroll
        for (int j = 0; j < 4; j++) {
            int p = j >> 1, h = j & 1;
            uint32_t mcol = (uint32_t)(wh * 32 + p * 16 + h * 8 + 2 * tig);
            uint32_t o0 = OFF_S + (uint32_t)(wq * 16 + gq) * G_PITCH + mcol * 2u;
            uint32_t hh, ll;
            split2(sacc[j][0] * invN, sacc[j][1] * invN, hh, ll);
            *(uint32_t*)(smem + o0) = hh;
            *(uint32_t*)(smem + o0 + S_LO) = ll;
            split2(sacc[j][2] * invN, sacc[j][3] * invN, hh, ll);
            uint32_t o1 = o0 + 8u * G_PITCH;
            *(uint32_t*)(smem + o1) = hh;
            *(uint32_t*)(smem + o1 + S_LO) = ll;
        }
        CP_WAIT0();         // Phi[it+1] (and any pending G) arrived
        __syncthreads();    // S visible to all warps

        // ---- Phase B: Y[16 n][64 ci] += S . G  (K=64)
#pragma unroll
        for (int kk = 0; kk < 4; kk++) {
            uint32_t Ah[4], Al[4];
            LDM_X4(Ah, aSBase + 32u * kk);
            LDM_X4(Al, aSBase + S_LO + 32u * kk);
#pragma unroll
            for (int cp = 0; cp < 4; cp++) {
                uint32_t bh[4], bl[4];
                uint32_t ga = gBase + (uint32_t)((wh * 64 + 16 * cp)) * G_PITCH +
                              32u * kk;
                LDM_X4(bh, ga);
                LDM_X4(bl, ga + G_LO);
                mma6(yacc[2 * cp], yacc[2 * cp + 1], Ah, Al, bh, bl);
            }
        }
        __syncthreads();    // MMA2 done: sS and G buffer reusable

        // issue G[it+1] now (single buffer, free after the sync above)
        if (it + 1 < NCHUNK)
            load_g(sb, bb, (it + 1) * MT, tid, Ghi, Glo);
    }

    // ---- store Y[b][n][ci] as bf16 hi/lo
    const size_t yb = ((size_t)bb * NPIX + n0 + wq * 16 + gq) * CI;
#pragma unroll
    for (int j = 0; j < 8; j++) {
        int ci = wh * 64 + (j >> 1) * 16 + (j & 1) * 8 + 2 * tig;
        uint32_t h, l;
        size_t o = yb + ci;
        split2(yacc[j][0], yacc[j][1], h, l);
        *(uint32_t*)(Yhi + o) = h; *(uint32_t*)(Ylo + o) = l;
        split2(yacc[j][2], yacc[j][3], h, l);
        o += (size_t)8 * CI;
        *(uint32_t*)(Yhi + o) = h; *(uint32_t*)(Ylo + o) = l;
    }
}

// ---------------------------------------------------------------------------
// final (HMMA): out[b][c][n] = A[c]*(W_w[c,:] . Y[n,:]) + Bb[c]
// ---------------------------------------------------------------------------
#define FN_PITCH 272u
#define FN_WH 0u
#define FN_WL 34816u
#define FN_YH 69632u
#define FN_YL 104448u
#define FN_SMEM 139264u

__global__ __launch_bounds__(256)
void final_mma_kernel(const __nv_bfloat16* __restrict__ Yhi,
                      const __nv_bfloat16* __restrict__ Ylo,
                      const float* __restrict__ Ww,
                      const float* __restrict__ gamma,
                      const float* __restrict__ beta,
                      const float* __restrict__ mean,
                      const float* __restrict__ var,
                      float* __restrict__ out) {
    extern __shared__ char fsm[];
    const uint32_t sb = smem_u32(fsm);
    const int tid = threadIdx.x, lane = tid & 31, wid = tid >> 5;
    const int bb = blockIdx.z;
    const int c0 = blockIdx.y * 128;
    const int n0 = blockIdx.x * 128;

#pragma unroll
    for (int i = 0; i < 8; i++) {
        int idx = tid + i * 256;
        int r = idx >> 4, g = idx & 15;
        size_t so = ((size_t)bb * NPIX + n0 + r) * CI + 8 * g;
        uint32_t d = sb + FN_YH + (uint32_t)r * FN_PITCH + 16u * (uint32_t)g;
        CP16(d, Yhi + so);
        CP16(d + (FN_YL - FN_YH), Ylo + so);
    }
    CP_COMMIT();
#pragma unroll
    for (int i = 0; i < 16; i++) {
        int idx = tid + i * 256;
        int r = idx >> 5, c4 = idx & 31;
        float4 v = *(const float4*)&Ww[(size_t)(c0 + r) * CI + 4 * c4];
        uint2 H, L;
        H.x = pk(v.x, v.y); H.y = pk(v.z, v.w);
        L.x = pk(resid(v.x), resid(v.y)); L.y = pk(resid(v.z), resid(v.w));
        uint32_t o = (uint32_t)r * FN_PITCH + 8u * (uint32_t)c4;
        *(uint2*)(fsm + FN_WH + o) = H;
        *(uint2*)(fsm + FN_WL + o) = L;
    }
    CP_WAIT0();
    __syncthreads();

    const int lm = lane & 7, mid = lane >> 3;
    const int arow = (mid & 1) * 8 + lm, acolB = (mid >> 1) * 16;
    const int brow = (mid >> 1) * 8 + lm, bcolB = (mid & 1) * 16;

    uint32_t ah[8][4], al[8][4];
    const uint32_t aB = sb + FN_WH + (uint32_t)(wid * 16 + arow) * FN_PITCH + acolB;
#pragma unroll
    for (int kk = 0; kk < 8; kk++) {
        LDM_X4(ah[kk], aB + 32u * kk);
        LDM_X4(al[kk], aB + (FN_WL - FN_WH) + 32u * kk);
    }

    float yacc[16][4];
#pragma unroll
    for (int t = 0; t < 16; t++)
#pragma unroll
        for (int j = 0; j < 4; j++) yacc[t][j] = 0.f;

#pragma unroll
    for (int np = 0; np < 8; np++) {
        const uint32_t bB = sb + FN_YH +
            (uint32_t)(np * 16 + brow) * FN_PITCH + bcolB;
#pragma unroll
        for (int kk = 0; kk < 8; kk++) {
            uint32_t bh[4], bl[4];
            LDM_X4(bh, bB + 32u * kk);
            LDM_X4(bl, bB + (FN_YL - FN_YH) + 32u * kk);
            mma6(yacc[2 * np], yacc[2 * np + 1], ah[kk], al[kk], bh, bl);
        }
    }

    const int gq = lane >> 2, tig = lane & 3;
    const int cA = c0 + wid * 16 + gq;
    const int cB = cA + 8;
    float iA = rsqrtf(var[cA] + 1e-5f);
    float A0 = gamma[cA] * iA, B0 = beta[cA] - mean[cA] * A0;
    float iB = rsqrtf(var[cB] + 1e-5f);
    float A1 = gamma[cB] * iB, B1 = beta[cB] - mean[cB] * A1;

#pragma unroll
    for (int t = 0; t < 16; t++) {
        int n = n0 + (t >> 1) * 16 + (t & 1) * 8 + 2 * tig;
        size_t o0 = ((size_t)bb * C_IN + cA) * NPIX + n;
        size_t o1 = ((size_t)bb * C_IN + cB) * NPIX + n;
        *(float2*)(out + o0) = make_float2(yacc[t][0] * A0 + B0,
                                           yacc[t][1] * A0 + B0);
        *(float2*)(out + o1) = make_float2(yacc[t][2] * A1 + B1,
                                           yacc[t][3] * A1 + B1);
    }
}

// ---------------------------------------------------------------------------
// Launch
// ---------------------------------------------------------------------------
extern "C" void kernel_launch(void* const* d_in, const int* in_sizes, int n_in,
                              void* d_out, int out_size) {
    const float* a       = (const float*)d_in[0];
    const float* b       = (const float*)d_in[1];
    const float* theta_w = (const float*)d_in[2];
    const float* theta_b = (const float*)d_in[3];
    const float* phi_w   = (const float*)d_in[4];
    const float* phi_b   = (const float*)d_in[5];
    const float* g_w     = (const float*)d_in[6];
    const float* g_b     = (const float*)d_in[7];
    const float* W_w     = (const float*)d_in[8];
    const float* bn_g    = (const float*)d_in[9];
    const float* bn_be   = (const float*)d_in[10];
    const float* bn_m    = (const float*)d_in[11];
    const float* bn_v    = (const float*)d_in[12];
    float* out = (float*)d_out;

    __nv_bfloat16 *Thi, *Tlo, *Phh, *Phl, *Ghi, *Glo, *Yhi, *Ylo;
    cudaGetSymbolAddress((void**)&Thi, g_Thi);
    cudaGetSymbolAddress((void**)&Tlo, g_Tlo);
    cudaGetSymbolAddress((void**)&Phh, g_Phh);
    cudaGetSymbolAddress((void**)&Phl, g_Phl);
    cudaGetSymbolAddress((void**)&Ghi, g_Ghi);
    cudaGetSymbolAddress((void**)&Glo, g_Glo);
    cudaGetSymbolAddress((void**)&Yhi, g_Yhi);
    cudaGetSymbolAddress((void**)&Ylo, g_Ylo);

    cudaFuncSetAttribute(proj_mma_kernel<1>,
                         cudaFuncAttributeMaxDynamicSharedMemorySize, PJ_SMEM);
    cudaFuncSetAttribute(proj_mma_kernel<0>,
                         cudaFuncAttributeMaxDynamicSharedMemorySize, PJ_SMEM);
    cudaFuncSetAttribute(attn_hmma_kernel,
                         cudaFuncAttributeMaxDynamicSharedMemorySize, SMEM_BYTES);
    cudaFuncSetAttribute(final_mma_kernel,
                         cudaFuncAttributeMaxDynamicSharedMemorySize, FN_SMEM);

    dim3 projGrid(NPIX / 64, BATCH);
    proj_mma_kernel<1><<<projGrid, 256, PJ_SMEM>>>(a, theta_w, theta_b, Thi, Tlo);
    proj_mma_kernel<1><<<projGrid, 256, PJ_SMEM>>>(b, phi_w,   phi_b,   Phh, Phl);
    proj_mma_kernel<0><<<projGrid, 256, PJ_SMEM>>>(b, g_w,     g_b,     Ghi, Glo);

    dim3 attnGrid(NPIX / NT, BATCH);
    attn_hmma_kernel<<<attnGrid, 512, SMEM_BYTES>>>(Thi, Tlo, Phh, Phl,
                                                    Ghi, Glo, Yhi, Ylo);

    dim3 finGrid(NPIX / 128, C_IN / 128, BATCH);
    final_mma_kernel<<<finGrid, 256, FN_SMEM>>>(Yhi, Ylo, W_w, bn_g, bn_be,
                                                bn_m, bn_v, out);
}

// round 13
// speedup vs baseline: 2.7723x; 2.7723x over previous
#include <cuda_runtime.h>
#include <cuda_bf16.h>
#include <cstdint>
#include <cstddef>

// Problem constants
#define BATCH 4
#define C_IN  256
#define CI    128
#define NPIX  4096   // 64*64
#define MS    16     // split-K factor for M = Phi^T G

// ---------------------------------------------------------------------------
// Scratch (allocation-free: __device__ globals)
// ---------------------------------------------------------------------------
__device__ __nv_bfloat16 g_Thi[(size_t)BATCH * NPIX * CI];  // theta(a) [B][n][ci]
__device__ __nv_bfloat16 g_Tlo[(size_t)BATCH * NPIX * CI];
__device__ __nv_bfloat16 g_Pch[(size_t)BATCH * CI * NPIX];  // phi(b)   [B][ci][m]
__device__ __nv_bfloat16 g_Pcl[(size_t)BATCH * CI * NPIX];
__device__ __nv_bfloat16 g_Gch[(size_t)BATCH * CI * NPIX];  // g(b)     [B][ci][m]
__device__ __nv_bfloat16 g_Gcl[(size_t)BATCH * CI * NPIX];
__device__ float g_Mpart[(size_t)BATCH * MS * CI * CI];     // split-K partials
__device__ float g_Mred [(size_t)BATCH * CI * CI];          // M[b][k][c]
__device__ __nv_bfloat16 g_W2h[(size_t)BATCH * C_IN * CI];  // W2[b][co][k]
__device__ __nv_bfloat16 g_W2l[(size_t)BATCH * C_IN * CI];

// ---------------------------------------------------------------------------
// PTX helpers (baseline features only: valid under compute_103)
// ---------------------------------------------------------------------------
__device__ __forceinline__ uint32_t smem_u32(const void* p) {
    uint32_t a;
    asm("{ .reg .u64 t; cvta.to.shared.u64 t, %1; cvt.u32.u64 %0, t; }"
        : "=r"(a) : "l"(p));
    return a;
}

#define LDM_X4(r, a)                                                          \
    asm volatile("ldmatrix.sync.aligned.m8n8.x4.shared.b16 {%0,%1,%2,%3}, [%4];" \
        : "=r"((r)[0]), "=r"((r)[1]), "=r"((r)[2]), "=r"((r)[3]) : "r"(a))

__device__ __forceinline__ void mma16816(float* d, const uint32_t* a,
                                         uint32_t b0, uint32_t b1) {
    asm("mma.sync.aligned.m16n8k16.row.col.f32.bf16.bf16.f32 "
        "{%0,%1,%2,%3}, {%4,%5,%6,%7}, {%8,%9}, {%0,%1,%2,%3};"
        : "+f"(d[0]), "+f"(d[1]), "+f"(d[2]), "+f"(d[3])
        : "r"(a[0]), "r"(a[1]), "r"(a[2]), "r"(a[3]), "r"(b0), "r"(b1));
}

#define CP16(dst, src)                                                        \
    asm volatile("cp.async.cg.shared.global [%0], [%1], 16;"                  \
                 :: "r"(dst), "l"(src) : "memory")
#define CP_COMMIT() asm volatile("cp.async.commit_group;" ::: "memory")
#define CP_WAIT0()  asm volatile("cp.async.wait_group 0;" ::: "memory")

// bf16 split helpers
__device__ __forceinline__ uint32_t pk(float a, float b) {
    uint32_t ua = (uint32_t)__bfloat16_as_ushort(__float2bfloat16(a));
    uint32_t ub = (uint32_t)__bfloat16_as_ushort(__float2bfloat16(b));
    return ua | (ub << 16);
}
__device__ __forceinline__ float resid(float v) {
    return v - __bfloat162float(__float2bfloat16(v));
}
__device__ __forceinline__ void split2(float a, float b,
                                       uint32_t& hi, uint32_t& lo) {
    __nv_bfloat16 ha = __float2bfloat16(a), hb = __float2bfloat16(b);
    hi = (uint32_t)__bfloat16_as_ushort(ha) |
         ((uint32_t)__bfloat16_as_ushort(hb) << 16);
    lo = pk(a - __bfloat162float(ha), b - __bfloat162float(hb));
}

// 6 split-bf16 MMAs for one 16-col B panel, interleaved accumulators
__device__ __forceinline__ void mma6(float* d0, float* d1,
                                     const uint32_t* ah, const uint32_t* al,
                                     const uint32_t* bh, const uint32_t* bl) {
    mma16816(d0, ah, bh[0], bh[1]);
    mma16816(d1, ah, bh[2], bh[3]);
    mma16816(d0, ah, bl[0], bl[1]);
    mma16816(d1, ah, bl[2], bl[3]);
    mma16816(d0, al, bh[0], bh[1]);
    mma16816(d1, al, bh[2], bh[3]);
}

// ---------------------------------------------------------------------------
// proj (HMMA): out = w[CI,C] @ x[b][C,:] + bias, split-bf16 emulation.
// TRANS=1 -> out[b][n][ci] (theta) ; TRANS=0 -> out[b][ci][n] (phi, g)
// ---------------------------------------------------------------------------
#define PJ_PITCH 528u
#define PJ_XH 0u
#define PJ_XL 33792u
#define PJ_WH 67584u
#define PJ_WL 135168u
#define PJ_SMEM 202752u

template<int TRANS>
__global__ __launch_bounds__(256)
void proj_mma_kernel(const float* __restrict__ x, const float* __restrict__ w,
                     const float* __restrict__ bias,
                     __nv_bfloat16* __restrict__ outHi,
                     __nv_bfloat16* __restrict__ outLo) {
    extern __shared__ char psm[];
    const uint32_t sb = smem_u32(psm);
    const int tid = threadIdx.x, lane = tid & 31, wid = tid >> 5;
    const int bb = blockIdx.y, n0 = blockIdx.x * 64;

#pragma unroll
    for (int i = 0; i < 16; i++) {
        int idx = tid + i * 256;
        int c = idx >> 4, n4 = idx & 15;
        float4 v = *(const float4*)&x[((size_t)bb * C_IN + c) * NPIX + n0 + 4 * n4];
        float vv[4] = {v.x, v.y, v.z, v.w};
#pragma unroll
        for (int j = 0; j < 4; j++) {
            __nv_bfloat16 h = __float2bfloat16(vv[j]);
            uint32_t o = (uint32_t)(4 * n4 + j) * PJ_PITCH + 2u * (uint32_t)c;
            *(unsigned short*)(psm + PJ_XH + o) = __bfloat16_as_ushort(h);
            *(unsigned short*)(psm + PJ_XL + o) =
                __bfloat16_as_ushort(__float2bfloat16(vv[j] - __bfloat162float(h)));
        }
    }
#pragma unroll
    for (int i = 0; i < 32; i++) {
        int idx = tid + i * 256;
        int r = idx >> 6, c4 = idx & 63;
        float4 v = *(const float4*)&w[(size_t)r * C_IN + 4 * c4];
        uint2 H, L;
        H.x = pk(v.x, v.y); H.y = pk(v.z, v.w);
        L.x = pk(resid(v.x), resid(v.y)); L.y = pk(resid(v.z), resid(v.w));
        uint32_t o = (uint32_t)r * PJ_PITCH + 8u * (uint32_t)c4;
        *(uint2*)(psm + PJ_WH + o) = H;
        *(uint2*)(psm + PJ_WL + o) = L;
    }
    __syncthreads();

    const int lm = lane & 7, mid = lane >> 3;
    const int arow = (mid & 1) * 8 + lm, acolB = (mid >> 1) * 16;
    const int brow = (mid >> 1) * 8 + lm, bcolB = (mid & 1) * 16;

    uint32_t aBase, bBase, aLd, bLd;
    if (TRANS) {
        int mi = wid & 3, ch = wid >> 2;
        aBase = sb + PJ_XH + (uint32_t)(mi * 16 + arow) * PJ_PITCH + acolB;
        bBase = sb + PJ_WH + (uint32_t)(ch * 64 + brow) * PJ_PITCH + bcolB;
        aLd = PJ_XL - PJ_XH; bLd = PJ_WL - PJ_WH;
    } else {
        aBase = sb + PJ_WH + (uint32_t)(wid * 16 + arow) * PJ_PITCH + acolB;
        bBase = sb + PJ_XH + (uint32_t)brow * PJ_PITCH + bcolB;
        aLd = PJ_WL - PJ_WH; bLd = PJ_XL - PJ_XH;
    }

    float acc[8][4];
#pragma unroll
    for (int j = 0; j < 8; j++)
#pragma unroll
        for (int q = 0; q < 4; q++) acc[j][q] = 0.f;

#pragma unroll 4
    for (int kk = 0; kk < 16; kk++) {
        uint32_t ah[4], al[4];
        LDM_X4(ah, aBase + 32u * kk);
        LDM_X4(al, aBase + aLd + 32u * kk);
#pragma unroll
        for (int p = 0; p < 4; p++) {
            uint32_t bh[4], bl[4];
            uint32_t ba = bBase + (uint32_t)(16 * p) * PJ_PITCH + 32u * kk;
            LDM_X4(bh, ba);
            LDM_X4(bl, ba + bLd);
            mma6(acc[2 * p], acc[2 * p + 1], ah, al, bh, bl);
        }
    }

    const int gq = lane >> 2, tig = lane & 3;
    if (TRANS) {
        int mi = wid & 3, ch = wid >> 2;
        int nA = n0 + mi * 16 + gq;
#pragma unroll
        for (int j = 0; j < 8; j++) {
            int ci = ch * 64 + j * 8 + 2 * tig;
            float b0 = bias[ci], b1 = bias[ci + 1];
            uint32_t h, l;
            size_t o = ((size_t)bb * NPIX + nA) * CI + ci;
            split2(acc[j][0] + b0, acc[j][1] + b1, h, l);
            *(uint32_t*)(outHi + o) = h; *(uint32_t*)(outLo + o) = l;
            split2(acc[j][2] + b0, acc[j][3] + b1, h, l);
            o += (size_t)8 * CI;
            *(uint32_t*)(outHi + o) = h; *(uint32_t*)(outLo + o) = l;
        }
    } else {
        int ciA = wid * 16 + gq;
        float b0 = bias[ciA], b1 = bias[ciA + 8];
#pragma unroll
        for (int j = 0; j < 8; j++) {
            int n = n0 + j * 8 + 2 * tig;
            uint32_t h, l;
            size_t o = ((size_t)bb * CI + ciA) * NPIX + n;
            split2(acc[j][0] + b0, acc[j][1] + b0, h, l);
            *(uint32_t*)(outHi + o) = h; *(uint32_t*)(outLo + o) = l;
            split2(acc[j][2] + b1, acc[j][3] + b1, h, l);
            o += (size_t)8 * NPIX;
            *(uint32_t*)(outHi + o) = h; *(uint32_t*)(outLo + o) = l;
        }
    }
}

// ---------------------------------------------------------------------------
// M partial (HMMA): Mpart[b][s][k][c] = sum_{m in slice s} Phi[k][m] * G[c][m]
// grid (MS, B), 256 thr. m-slice = 256, chunks of 64, double-buffered.
// smem buf: Phi [128][64] hi(+0)/lo(+18432), G hi(+36864)/lo(+55296); pitch 144.
// ---------------------------------------------------------------------------
#define MP_BUF  73728u
#define MP_SMEM 147456u

__device__ __forceinline__ void mp_load(uint32_t sb, int buf, int bb, int m0,
                                        int tid,
                                        const __nv_bfloat16* Phh,
                                        const __nv_bfloat16* Phl,
                                        const __nv_bfloat16* Ghi,
                                        const __nv_bfloat16* Glo) {
    uint32_t bo = sb + (uint32_t)buf * MP_BUF;
#pragma unroll
    for (int i = 0; i < 4; i++) {
        int idx = tid + i * 256;
        int ci = idx >> 3, m8 = idx & 7;
        size_t so = ((size_t)(bb * CI + ci)) * NPIX + m0 + m8 * 8;
        uint32_t d = bo + (uint32_t)ci * 144u + (uint32_t)m8 * 16u;
        CP16(d,          Phh + so);
        CP16(d + 18432u, Phl + so);
        CP16(d + 36864u, Ghi + so);
        CP16(d + 55296u, Glo + so);
    }
}

__global__ __launch_bounds__(256, 1)
void mpart_kernel(const __nv_bfloat16* __restrict__ Phh,
                  const __nv_bfloat16* __restrict__ Phl,
                  const __nv_bfloat16* __restrict__ Ghi,
                  const __nv_bfloat16* __restrict__ Glo,
                  float* __restrict__ Mpart) {
    extern __shared__ char msm[];
    const uint32_t sb = smem_u32(msm);
    const int tid = threadIdx.x, lane = tid & 31, wq = tid >> 5;
    const int ss = blockIdx.x, bb = blockIdx.y;
    const int m0base = ss * (NPIX / MS);

    const int lm = lane & 7, mid = lane >> 3;
    const int arow = (mid & 1) * 8 + lm, acol = (mid >> 1) * 16;
    const int brow = (mid >> 1) * 8 + lm, bcol = (mid & 1) * 16;
    const int gq = lane >> 2, tig = lane & 3;

    mp_load(sb, 0, bb, m0base, tid, Phh, Phl, Ghi, Glo);
    CP_COMMIT(); CP_WAIT0();
    __syncthreads();

    float acc[16][4];
#pragma unroll
    for (int t = 0; t < 16; t++)
#pragma unroll
        for (int q = 0; q < 4; q++) acc[t][q] = 0.f;

    for (int c = 0; c < 4; c++) {
        const int buf = c & 1;
        if (c + 1 < 4) {
            mp_load(sb, buf ^ 1, bb, m0base + (c + 1) * 64, tid,
                    Phh, Phl, Ghi, Glo);
            CP_COMMIT();
        }
        const uint32_t aB = sb + (uint32_t)buf * MP_BUF +
            (uint32_t)(wq * 16 + arow) * 144u + (uint32_t)acol;
        const uint32_t bB = sb + (uint32_t)buf * MP_BUF + 36864u +
            (uint32_t)brow * 144u + (uint32_t)bcol;
#pragma unroll
        for (int kk = 0; kk < 4; kk++) {
            uint32_t ah[4], al[4];
            LDM_X4(ah, aB + 32u * kk);
            LDM_X4(al, aB + 18432u + 32u * kk);
#pragma unroll
            for (int cp = 0; cp < 8; cp++) {
                uint32_t bh[4], bl[4];
                uint32_t ga = bB + (uint32_t)(16 * cp) * 144u + 32u * kk;
                LDM_X4(bh, ga);
                LDM_X4(bl, ga + 18432u);
                mma6(acc[2 * cp], acc[2 * cp + 1], ah, al, bh, bl);
            }
        }
        if (c + 1 < 4) CP_WAIT0();
        __syncthreads();
    }

    // write partials: row k = wq*16+gq (+8), col c = cp*16 + {0,8} + 2tig
    float* dst = Mpart +
        (((size_t)bb * MS + ss) * CI + wq * 16 + gq) * CI;
#pragma unroll
    for (int j = 0; j < 8; j++) {
        int cc = j * 16 + 2 * tig;
        *(float2*)(dst + cc)            = make_float2(acc[2*j][0],   acc[2*j][1]);
        *(float2*)(dst + cc + 8)        = make_float2(acc[2*j+1][0], acc[2*j+1][1]);
        *(float2*)(dst + 8*CI + cc)     = make_float2(acc[2*j][2],   acc[2*j][3]);
        *(float2*)(dst + 8*CI + cc + 8) = make_float2(acc[2*j+1][2], acc[2*j+1][3]);
    }
}

// ---------------------------------------------------------------------------
// M reduce: Mred[b][k][c] = sum_s Mpart[b][s][k][c]
// ---------------------------------------------------------------------------
__global__ __launch_bounds__(256)
void mred_kernel(const float* __restrict__ Mpart, float* __restrict__ Mred) {
    int gid = blockIdx.x * 256 + threadIdx.x;   // 65536 total
    int b = gid >> 14, rem = gid & 16383;
    const float* p = Mpart + ((size_t)b * MS) * 16384 + rem;
    float v = 0.f;
#pragma unroll
    for (int s = 0; s < MS; s++) v += p[(size_t)s * 16384];
    Mred[gid] = v;
}

// ---------------------------------------------------------------------------
// W2: W2[b][co][k] = bnA[co] * (1/N) * sum_c Ww[co][c] * Mred[b][k][c]
// grid (16 co-tiles, B), 256 thr. smem: M[b] staged [128][132] fp32.
// ---------------------------------------------------------------------------
#define W2_SMEM (128 * 132 * 4)

__global__ __launch_bounds__(256)
void w2_kernel(const float* __restrict__ Mred, const float* __restrict__ Ww,
               const float* __restrict__ gamma, const float* __restrict__ var,
               __nv_bfloat16* __restrict__ W2hi,
               __nv_bfloat16* __restrict__ W2lo) {
    extern __shared__ float sM[];   // [128][132]
    const int tid = threadIdx.x;
    const int co0 = blockIdx.x * 16, bb = blockIdx.y;
    const float* Mb = Mred + (size_t)bb * 16384;
#pragma unroll
    for (int i = 0; i < 16; i++) {
        int f4 = tid + i * 256;     // 4096 float4
        int k = f4 >> 5, c4 = f4 & 31;
        float4 v = *(const float4*)(Mb + k * 128 + 4 * c4);
        *(float4*)(sM + k * 132 + 4 * c4) = v;
    }
    __syncthreads();
    const float invN = 1.0f / (float)NPIX;
#pragma unroll
    for (int p = 0; p < 8; p++) {
        int oid = tid + p * 256;
        int co = co0 + (oid >> 7), k = oid & 127;
        const float* wr = Ww + (size_t)co * CI;
        const float* mr = sM + k * 132;
        float s = 0.f;
#pragma unroll 8
        for (int c = 0; c < 128; c++) s += wr[c] * mr[c];
        float A = gamma[co] * rsqrtf(var[co] + 1e-5f) * invN;
        float v = s * A;
        __nv_bfloat16 h = __float2bfloat16(v);
        size_t o = ((size_t)bb * C_IN + co) * CI + k;
        W2hi[o] = h;
        W2lo[o] = __float2bfloat16(v - __bfloat162float(h));
    }
}

// ---------------------------------------------------------------------------
// out (HMMA): out[b][co][n] = sum_k W2[b][co][k] * T[n][k] + Bb[co]
//   (bn scale already folded into W2; Bb = beta - mean*A)
// CTA tile [128 co][128 n], K=128. pitch 272.
// ---------------------------------------------------------------------------
#define FN_PITCH 272u
#define FN_WH 0u
#define FN_WL 34816u
#define FN_YH 69632u
#define FN_YL 104448u
#define FN_SMEM 139264u

__global__ __launch_bounds__(256)
void out_mma_kernel(const __nv_bfloat16* __restrict__ Thi,
                    const __nv_bfloat16* __restrict__ Tlo,
                    const __nv_bfloat16* __restrict__ W2hi,
                    const __nv_bfloat16* __restrict__ W2lo,
                    const float* __restrict__ gamma,
                    const float* __restrict__ beta,
                    const float* __restrict__ mean,
                    const float* __restrict__ var,
                    float* __restrict__ out) {
    extern __shared__ char fsm[];
    const uint32_t sb = smem_u32(fsm);
    const int tid = threadIdx.x, lane = tid & 31, wid = tid >> 5;
    const int bb = blockIdx.z;
    const int c0 = blockIdx.y * 128;
    const int n0 = blockIdx.x * 128;

    // stage A = W2[b] rows c0..c0+127 (hi/lo) : 128 rows x 16 granules each
#pragma unroll
    for (int i = 0; i < 8; i++) {
        int idx = tid + i * 256;
        int r = idx >> 4, g = idx & 15;
        size_t so = ((size_t)bb * C_IN + c0 + r) * CI + 8 * g;
        uint32_t d = sb + FN_WH + (uint32_t)r * FN_PITCH + 16u * (uint32_t)g;
        CP16(d, W2hi + so);
        CP16(d + (FN_WL - FN_WH), W2lo + so);
    }
    // stage B = T rows n0..n0+127 (hi/lo)
#pragma unroll
    for (int i = 0; i < 8; i++) {
        int idx = tid + i * 256;
        int r = idx >> 4, g = idx & 15;
        size_t so = ((size_t)bb * NPIX + n0 + r) * CI + 8 * g;
        uint32_t d = sb + FN_YH + (uint32_t)r * FN_PITCH + 16u * (uint32_t)g;
        CP16(d, Thi + so);
        CP16(d + (FN_YL - FN_YH), Tlo + so);
    }
    CP_COMMIT();
    CP_WAIT0();
    __syncthreads();

    const int lm = lane & 7, mid = lane >> 3;
    const int arow = (mid & 1) * 8 + lm, acolB = (mid >> 1) * 16;
    const int brow = (mid >> 1) * 8 + lm, bcolB = (mid & 1) * 16;

    uint32_t ah[8][4], al[8][4];
    const uint32_t aB = sb + FN_WH + (uint32_t)(wid * 16 + arow) * FN_PITCH + acolB;
#pragma unroll
    for (int kk = 0; kk < 8; kk++) {
        LDM_X4(ah[kk], aB + 32u * kk);
        LDM_X4(al[kk], aB + (FN_WL - FN_WH) + 32u * kk);
    }

    float yacc[16][4];
#pragma unroll
    for (int t = 0; t < 16; t++)
#pragma unroll
        for (int j = 0; j < 4; j++) yacc[t][j] = 0.f;

#pragma unroll
    for (int np = 0; np < 8; np++) {
        const uint32_t bB = sb + FN_YH +
            (uint32_t)(np * 16 + brow) * FN_PITCH + bcolB;
#pragma unroll
        for (int kk = 0; kk < 8; kk++) {
            uint32_t bh[4], bl[4];
            LDM_X4(bh, bB + 32u * kk);
            LDM_X4(bl, bB + (FN_YL - FN_YH) + 32u * kk);
            mma6(yacc[2 * np], yacc[2 * np + 1], ah[kk], al[kk], bh, bl);
        }
    }

    const int gq = lane >> 2, tig = lane & 3;
    const int cA = c0 + wid * 16 + gq;
    const int cB = cA + 8;
    float iA = rsqrtf(var[cA] + 1e-5f);
    float B0 = beta[cA] - mean[cA] * (gamma[cA] * iA);
    float iB = rsqrtf(var[cB] + 1e-5f);
    float B1 = beta[cB] - mean[cB] * (gamma[cB] * iB);

#pragma unroll
    for (int t = 0; t < 16; t++) {
        int n = n0 + (t >> 1) * 16 + (t & 1) * 8 + 2 * tig;
        size_t o0 = ((size_t)bb * C_IN + cA) * NPIX + n;
        size_t o1 = ((size_t)bb * C_IN + cB) * NPIX + n;
        *(float2*)(out + o0) = make_float2(yacc[t][0] + B0, yacc[t][1] + B0);
        *(float2*)(out + o1) = make_float2(yacc[t][2] + B1, yacc[t][3] + B1);
    }
}

// ---------------------------------------------------------------------------
// Launch
// ---------------------------------------------------------------------------
extern "C" void kernel_launch(void* const* d_in, const int* in_sizes, int n_in,
                              void* d_out, int out_size) {
    const float* a       = (const float*)d_in[0];
    const float* b       = (const float*)d_in[1];
    const float* theta_w = (const float*)d_in[2];
    const float* theta_b = (const float*)d_in[3];
    const float* phi_w   = (const float*)d_in[4];
    const float* phi_b   = (const float*)d_in[5];
    const float* g_w     = (const float*)d_in[6];
    const float* g_b     = (const float*)d_in[7];
    const float* W_w     = (const float*)d_in[8];
    const float* bn_g    = (const float*)d_in[9];
    const float* bn_be   = (const float*)d_in[10];
    const float* bn_m    = (const float*)d_in[11];
    const float* bn_v    = (const float*)d_in[12];
    float* out = (float*)d_out;

    __nv_bfloat16 *Thi, *Tlo, *Pch, *Pcl, *Gch, *Gcl, *W2h, *W2l;
    float *Mpart, *Mred;
    cudaGetSymbolAddress((void**)&Thi, g_Thi);
    cudaGetSymbolAddress((void**)&Tlo, g_Tlo);
    cudaGetSymbolAddress((void**)&Pch, g_Pch);
    cudaGetSymbolAddress((void**)&Pcl, g_Pcl);
    cudaGetSymbolAddress((void**)&Gch, g_Gch);
    cudaGetSymbolAddress((void**)&Gcl, g_Gcl);
    cudaGetSymbolAddress((void**)&Mpart, g_Mpart);
    cudaGetSymbolAddress((void**)&Mred, g_Mred);
    cudaGetSymbolAddress((void**)&W2h, g_W2h);
    cudaGetSymbolAddress((void**)&W2l, g_W2l);

    cudaFuncSetAttribute(proj_mma_kernel<1>,
                         cudaFuncAttributeMaxDynamicSharedMemorySize, PJ_SMEM);
    cudaFuncSetAttribute(proj_mma_kernel<0>,
                         cudaFuncAttributeMaxDynamicSharedMemorySize, PJ_SMEM);
    cudaFuncSetAttribute(mpart_kernel,
                         cudaFuncAttributeMaxDynamicSharedMemorySize, MP_SMEM);
    cudaFuncSetAttribute(w2_kernel,
                         cudaFuncAttributeMaxDynamicSharedMemorySize, W2_SMEM);
    cudaFuncSetAttribute(out_mma_kernel,
                         cudaFuncAttributeMaxDynamicSharedMemorySize, FN_SMEM);

    dim3 projGrid(NPIX / 64, BATCH);
    proj_mma_kernel<1><<<projGrid, 256, PJ_SMEM>>>(a, theta_w, theta_b, Thi, Tlo);
    proj_mma_kernel<0><<<projGrid, 256, PJ_SMEM>>>(b, phi_w,   phi_b,   Pch, Pcl);
    proj_mma_kernel<0><<<projGrid, 256, PJ_SMEM>>>(b, g_w,     g_b,     Gch, Gcl);

    dim3 mpGrid(MS, BATCH);
    mpart_kernel<<<mpGrid, 256, MP_SMEM>>>(Pch, Pcl, Gch, Gcl, Mpart);

    mred_kernel<<<BATCH * CI * CI / 256, 256>>>(Mpart, Mred);

    dim3 w2Grid(C_IN / 16, BATCH);
    w2_kernel<<<w2Grid, 256, W2_SMEM>>>(Mred, W_w, bn_g, bn_v, W2h, W2l);

    dim3 outGrid(NPIX / 128, C_IN / 128, BATCH);
    out_mma_kernel<<<outGrid, 256, FN_SMEM>>>(Thi, Tlo, W2h, W2l,
                                              bn_g, bn_be, bn_m, bn_v, out);
}